// round 6
// baseline (speedup 1.0000x reference)
#include <cuda_runtime.h>
#include <cstdint>

// ---------------------------------------------------------------------------
// Problem dims
// ---------------------------------------------------------------------------
#define M_TOTAL 8192
#define K_IN    4096
#define N_OUT   11008

// GEMM tiling: 128x128x64 CTA, 8 warps @ 32x64 warp tiles, dual int8 sets
#define BM 128
#define BN 128
#define BK 64                    // int8 elems per k-stage (64B rows)
#define STAGES 4
#define K_ITERS (K_IN / BK)      // 64
#define M_TILES (M_TOTAL / BM)   // 64
#define N_TILES (N_OUT / BN)     // 86
#define GROUP_M 16

#define LDS_B 80                 // smem bytes per 64B row (+16B pad, ldsm conflict-free)
#define A_STG (2 * BM * LDS_B)   // hi rows [0,128) + lo rows [128,256): 20480
#define B_STG (BN * LDS_B)       // 10240
#define STG   (A_STG + B_STG)    // 30720
#define SMEM_TOTAL (STAGES * STG) // 122880

// ---------------------------------------------------------------------------
// Scratch (device globals: allocation-free kernel_launch)
// ---------------------------------------------------------------------------
__device__ __align__(256) int8_t g_Ah[(size_t)M_TOTAL * K_IN];  // activation hi int8
__device__ __align__(256) int8_t g_Al[(size_t)M_TOTAL * K_IN];  // activation lo int8 (x256)
__device__ __align__(256) int8_t g_Wq[(size_t)N_OUT * K_IN];    // weights int8
__device__ float g_s1[M_TOTAL];                                  // per-row activation scale
__device__ float g_sumx[M_TOTAL];                                // per-row sum of quantized x

// ---------------------------------------------------------------------------
// PTX helpers (sm_80 baseline only — compute_103 safe)
// ---------------------------------------------------------------------------
__device__ __forceinline__ uint32_t smem_u32(const void* p) {
    uint32_t a;
    asm("{ .reg .u64 t; cvta.to.shared.u64 t, %1; cvt.u32.u64 %0, t; }" : "=r"(a) : "l"(p));
    return a;
}
__device__ __forceinline__ void cp_async16(uint32_t dst, const void* src) {
    asm volatile("cp.async.cg.shared.global [%0], [%1], 16;" :: "r"(dst), "l"(src));
}
#define CP_COMMIT() asm volatile("cp.async.commit_group;")
#define CP_WAIT()   asm volatile("cp.async.wait_group 2;")   // STAGES-2

__device__ __forceinline__ void ldsm_x4(uint32_t (&r)[4], uint32_t addr) {
    asm volatile("ldmatrix.sync.aligned.m8n8.x4.shared.b16 {%0,%1,%2,%3}, [%4];"
                 : "=r"(r[0]), "=r"(r[1]), "=r"(r[2]), "=r"(r[3]) : "r"(addr));
}
// int8 IMMA: D(16x8,s32) += A(16x32,s8) * B(32x8,s8)
__device__ __forceinline__ void imma16832(int (&d)[4], const uint32_t (&a)[4],
                                          uint32_t b0, uint32_t b1) {
    asm volatile(
        "mma.sync.aligned.m16n8k32.row.col.s32.s8.s8.s32 "
        "{%0,%1,%2,%3}, {%4,%5,%6,%7}, {%8,%9}, {%0,%1,%2,%3};"
        : "+r"(d[0]), "+r"(d[1]), "+r"(d[2]), "+r"(d[3])
        : "r"(a[0]), "r"(a[1]), "r"(a[2]), "r"(a[3]), "r"(b0), "r"(b1));
}

__device__ __forceinline__ int clamp127(int v) {
    return v > 127 ? 127 : (v < -127 ? -127 : v);
}
__device__ __forceinline__ uint32_t pack4(int a, int b, int c, int d) {
    return (uint32_t)(uint8_t)(int8_t)a | ((uint32_t)(uint8_t)(int8_t)b << 8) |
           ((uint32_t)(uint8_t)(int8_t)c << 16) | ((uint32_t)(uint8_t)(int8_t)d << 24);
}

// ---------------------------------------------------------------------------
// Fused prep: blocks [0,M) quantize activations (hi+lo int8, scale, sum);
// blocks [M, M+N) pack weights int32 -> int8. Single launch (ncu -s 5 = gemm).
// ---------------------------------------------------------------------------
__global__ void __launch_bounds__(256) k_prep(const float* __restrict__ in,
                                              const int* __restrict__ q) {
    int b = blockIdx.x;
    int t = threadIdx.x;
    __shared__ float red[8];
    if (b < M_TOTAL) {
        const float4* src = reinterpret_cast<const float4*>(in + (size_t)b * K_IN);
        float4 v[4];
        float amax = 0.f;
#pragma unroll
        for (int i = 0; i < 4; i++) {
            v[i] = src[i * 256 + t];
            amax = fmaxf(amax, fmaxf(fmaxf(fabsf(v[i].x), fabsf(v[i].y)),
                                     fmaxf(fabsf(v[i].z), fabsf(v[i].w))));
        }
#pragma unroll
        for (int off = 16; off; off >>= 1)
            amax = fmaxf(amax, __shfl_xor_sync(0xFFFFFFFFu, amax, off));
        if ((t & 31) == 0) red[t >> 5] = amax;
        __syncthreads();
        amax = red[0];
#pragma unroll
        for (int i = 1; i < 8; i++) amax = fmaxf(amax, red[i]);

        float inv = (amax > 1e-20f) ? 127.f / amax : 0.f;
        float s1 = (amax > 1e-20f) ? amax / 127.f : 0.f;

        uint32_t* dh = reinterpret_cast<uint32_t*>(g_Ah + (size_t)b * K_IN);
        uint32_t* dl = reinterpret_cast<uint32_t*>(g_Al + (size_t)b * K_IN);
        float s = 0.f;
#pragma unroll
        for (int i = 0; i < 4; i++) {
            int e = i * 256 + t;
            float f[4] = {v[i].x, v[i].y, v[i].z, v[i].w};
            int q1[4], q2[4];
#pragma unroll
            for (int j = 0; j < 4; j++) {
                float xs = f[j] * inv;
                q1[j] = clamp127(__float2int_rn(xs));
                float r = xs - (float)q1[j];
                q2[j] = clamp127(__float2int_rn(r * 256.f));
                s += (float)q1[j] + (float)q2[j] * 0.00390625f;
            }
            dh[e] = pack4(q1[0], q1[1], q1[2], q1[3]);
            dl[e] = pack4(q2[0], q2[1], q2[2], q2[3]);
        }
        // block-reduce s
#pragma unroll
        for (int off = 16; off; off >>= 1) s += __shfl_xor_sync(0xFFFFFFFFu, s, off);
        __syncthreads();
        if ((t & 31) == 0) red[t >> 5] = s;
        __syncthreads();
        if (t == 0) {
            float tot = 0.f;
#pragma unroll
            for (int i = 0; i < 8; i++) tot += red[i];
            g_sumx[b] = tot * s1;
            g_s1[b] = s1;
        }
    } else {
        int row = b - M_TOTAL;
        const int4* src = reinterpret_cast<const int4*>(q + (size_t)row * K_IN);
        uint4* dst = reinterpret_cast<uint4*>(g_Wq + (size_t)row * K_IN);
        // 4096 ints per row -> 256 uint4 outs; each thread: 4 int4 reads, 1 uint4 write
        int4 a0 = src[t * 4 + 0], a1 = src[t * 4 + 1], a2 = src[t * 4 + 2], a3 = src[t * 4 + 3];
        uint4 o;
        o.x = pack4(a0.x, a0.y, a0.z, a0.w);
        o.y = pack4(a1.x, a1.y, a1.z, a1.w);
        o.z = pack4(a2.x, a2.y, a2.z, a2.w);
        o.w = pack4(a3.x, a3.y, a3.z, a3.w);
        dst[t] = o;
    }
}

// ---------------------------------------------------------------------------
// GEMM: dual-set int8 IMMA, 128x128x64 CTA, 8 warps @ 32x64, 4-stage cp.async
// ---------------------------------------------------------------------------
__device__ __forceinline__ void load_stage(uint32_t s_base, const int8_t* Ah,
                                           const int8_t* Al, const int8_t* Wg,
                                           int kt, int t) {
    int cc = (t & 3) * 16;       // byte offset within 64B row
    int r = t >> 2;              // 0..63
    size_t go = (size_t)kt * BK + cc;
    // A-hi rows r, r+64 -> smem rows r, r+64
    cp_async16(s_base + r * LDS_B + cc,               Ah + (size_t)r * K_IN + go);
    cp_async16(s_base + (r + 64) * LDS_B + cc,        Ah + (size_t)(r + 64) * K_IN + go);
    // A-lo rows -> smem rows 128+r, 192+r
    cp_async16(s_base + (r + 128) * LDS_B + cc,       Al + (size_t)r * K_IN + go);
    cp_async16(s_base + (r + 192) * LDS_B + cc,       Al + (size_t)(r + 64) * K_IN + go);
    // B rows r, r+64
    uint32_t sB = s_base + A_STG;
    cp_async16(sB + r * LDS_B + cc,                   Wg + (size_t)r * K_IN + go);
    cp_async16(sB + (r + 64) * LDS_B + cc,            Wg + (size_t)(r + 64) * K_IN + go);
}

__global__ void __launch_bounds__(256, 1) k_gemm(
    const int8_t* __restrict__ pAh, const int8_t* __restrict__ pAl,
    const int8_t* __restrict__ pW,
    float* __restrict__ out,
    const float* __restrict__ w_scale, const int* __restrict__ w_zp,
    const float* __restrict__ bias,
    const float* __restrict__ s1v, const float* __restrict__ sumx)
{
    extern __shared__ char smem[];
    uint32_t sm0 = smem_u32(smem);
    int t = threadIdx.x;
    int wid = t >> 5;
    int l = t & 31;

    // grouped rasterization (L2 reuse of W)
    int bid = blockIdx.x;
    const int group = GROUP_M * N_TILES;      // 1376
    int g0 = bid / group;
    int rem = bid - g0 * group;
    int mtile = g0 * GROUP_M + (rem % GROUP_M);
    int ntile = rem / GROUP_M;

    int mbase = (wid & 3) * 32;               // 4 warps in M (32 rows each)
    int nbase = (wid >> 2) * 64;              // 2 warps in N (64 cols each)

    const int8_t* Ah = pAh + (size_t)mtile * BM * K_IN;
    const int8_t* Al = pAl + (size_t)mtile * BM * K_IN;
    const int8_t* Wg = pW + (size_t)ntile * BN * K_IN;

    int acc[2][2][8][4];                      // [set][mi][nj][frag]
#pragma unroll
    for (int s = 0; s < 2; s++)
#pragma unroll
        for (int a = 0; a < 2; a++)
#pragma unroll
            for (int b = 0; b < 8; b++)
#pragma unroll
                for (int c = 0; c < 4; c++) acc[s][a][b][c] = 0;

    // prologue
#pragma unroll
    for (int s = 0; s < STAGES - 1; s++) {
        load_stage(sm0 + s * STG, Ah, Al, Wg, s, t);
        CP_COMMIT();
    }

    // lane-invariant ldmatrix address pieces (identical structure to fp16; 16B k-granule)
    uint32_t a_lane_off = (uint32_t)((l & 15) + mbase) * LDS_B + ((l >> 4) << 4);
    uint32_t b_lane_off = (uint32_t)((l & 7) + ((l >> 4) << 3) + nbase) * LDS_B
                        + (((l >> 3) & 1) << 4);

    int buf = 0;
    for (int kt = 0; kt < K_ITERS; kt++) {
        CP_WAIT();
        __syncthreads();

        uint32_t sA = sm0 + buf * STG;
        uint32_t sB = sA + A_STG;

        // load ALL fragments for this kt (k32=0 first so IMMAs can start early)
        uint32_t af[2][2][2][4];   // [k32][set][mi]
        uint32_t bfr[2][4][4];     // [k32][npair] -> (b0,b1) of 2 n-tiles
#pragma unroll
        for (int k32 = 0; k32 < 2; k32++) {
            uint32_t koff = (uint32_t)k32 * 32;
#pragma unroll
            for (int set = 0; set < 2; set++)
#pragma unroll
                for (int mi = 0; mi < 2; mi++)
                    ldsm_x4(af[k32][set][mi],
                            sA + koff + a_lane_off + (set * 128 + mi * 16) * LDS_B);
#pragma unroll
            for (int np = 0; np < 4; np++)
                ldsm_x4(bfr[k32][np], sB + koff + b_lane_off + np * 16 * LDS_B);
        }

        // producer for stage kt+STAGES-1
        int nstage = kt + STAGES - 1;
        if (nstage < K_ITERS) {
            int nbuf = buf + (STAGES - 1); if (nbuf >= STAGES) nbuf -= STAGES;
            load_stage(sm0 + nbuf * STG, Ah, Al, Wg, nstage, t);
        }
        CP_COMMIT();

        // 64 IMMAs per warp per kt
#pragma unroll
        for (int k32 = 0; k32 < 2; k32++)
#pragma unroll
            for (int set = 0; set < 2; set++)
#pragma unroll
                for (int mi = 0; mi < 2; mi++)
#pragma unroll
                    for (int np = 0; np < 4; np++) {
                        imma16832(acc[set][mi][2 * np],     af[k32][set][mi],
                                  bfr[k32][np][0], bfr[k32][np][1]);
                        imma16832(acc[set][mi][2 * np + 1], af[k32][set][mi],
                                  bfr[k32][np][2], bfr[k32][np][3]);
                    }

        if (++buf == STAGES) buf = 0;
    }

    // ------------------ epilogue ------------------
    int g = l >> 2;
    int t2 = (l & 3) << 1;

    float scx[8][2], zpx[8][2], bix[8][2];
#pragma unroll
    for (int nj = 0; nj < 8; nj++) {
        int n = ntile * BN + nbase + nj * 8 + t2;
        float2 sc = *reinterpret_cast<const float2*>(w_scale + n);
        int2   zp = *reinterpret_cast<const int2*>(w_zp + n);
        float2 bb = *reinterpret_cast<const float2*>(bias + n);
        scx[nj][0] = sc.x; scx[nj][1] = sc.y;
        zpx[nj][0] = (float)zp.x; zpx[nj][1] = (float)zp.y;
        bix[nj][0] = bb.x; bix[nj][1] = bb.y;
    }

#pragma unroll
    for (int mi = 0; mi < 2; mi++) {
        int m0 = mtile * BM + mbase + mi * 16 + g;
        float sa0 = s1v[m0], sa1 = s1v[m0 + 8];
        float sx0 = sumx[m0], sx1 = sumx[m0 + 8];
        float* o0 = out + (size_t)m0 * N_OUT + ntile * BN + nbase + t2;
        float* o1 = o0 + (size_t)8 * N_OUT;
#pragma unroll
        for (int nj = 0; nj < 8; nj++) {
            float f00 = ((float)acc[0][mi][nj][0] + (float)acc[1][mi][nj][0] * 0.00390625f) * sa0;
            float f01 = ((float)acc[0][mi][nj][1] + (float)acc[1][mi][nj][1] * 0.00390625f) * sa0;
            float f10 = ((float)acc[0][mi][nj][2] + (float)acc[1][mi][nj][2] * 0.00390625f) * sa1;
            float f11 = ((float)acc[0][mi][nj][3] + (float)acc[1][mi][nj][3] * 0.00390625f) * sa1;
            float2 v0, v1;
            v0.x = (f00 - zpx[nj][0] * sx0) * scx[nj][0] + bix[nj][0];
            v0.y = (f01 - zpx[nj][1] * sx0) * scx[nj][1] + bix[nj][1];
            v1.x = (f10 - zpx[nj][0] * sx1) * scx[nj][0] + bix[nj][0];
            v1.y = (f11 - zpx[nj][1] * sx1) * scx[nj][1] + bix[nj][1];
            *reinterpret_cast<float2*>(o0 + nj * 8) = v0;
            *reinterpret_cast<float2*>(o1 + nj * 8) = v1;
        }
    }
}

// ---------------------------------------------------------------------------
// Host
// ---------------------------------------------------------------------------
extern "C" void kernel_launch(void* const* d_in, const int* in_sizes, int n_in,
                              void* d_out, int out_size) {
    const float* input   = (const float*)d_in[0];
    const int*   qweight = (const int*)d_in[1];
    const float* w_scale = (const float*)d_in[2];
    const int*   w_zp    = (const int*)d_in[3];
    const float* bias    = (const float*)d_in[4];
    float*       out     = (float*)d_out;

    void *pAh = nullptr, *pAl = nullptr, *pW = nullptr, *pS1 = nullptr, *pSx = nullptr;
    cudaGetSymbolAddress(&pAh, g_Ah);
    cudaGetSymbolAddress(&pAl, g_Al);
    cudaGetSymbolAddress(&pW, g_Wq);
    cudaGetSymbolAddress(&pS1, g_s1);
    cudaGetSymbolAddress(&pSx, g_sumx);

    k_prep<<<M_TOTAL + N_OUT, 256>>>(input, qweight);

    cudaFuncSetAttribute(k_gemm, cudaFuncAttributeMaxDynamicSharedMemorySize, SMEM_TOTAL);
    k_gemm<<<M_TILES * N_TILES, 256, SMEM_TOTAL>>>(
        (const int8_t*)pAh, (const int8_t*)pAl, (const int8_t*)pW,
        out, w_scale, w_zp, bias, (const float*)pS1, (const float*)pSx);
}

// round 7
// speedup vs baseline: 4.3941x; 4.3941x over previous
#include <cuda_runtime.h>
#include <cuda_fp16.h>
#include <cstdint>

// ---------------------------------------------------------------------------
// Problem dims
// ---------------------------------------------------------------------------
#define M_TOTAL 8192
#define K_IN    4096
#define N_OUT   11008

// GEMM tiling: 128x256x32 CTA, 8 warps @ 64x64 warp tiles, 1 CTA/SM
#define BM 128
#define BN 256
#define BK 32                    // halfs per k-stage
#define STAGES 6                 // 2-kt sync window needs the extra slack
#define K_ITERS (K_IN / BK)      // 128
#define M_TILES (M_TOTAL / BM)   // 64
#define N_TILES (N_OUT / BN)     // 43
#define GROUP_M 16

#define LDS_B 80                 // smem bytes per 32-half row (64B + 16B pad)
#define A_STG (BM * LDS_B)       // 10240
#define B_STG (BN * LDS_B)       // 20480
#define STG   (A_STG + B_STG)    // 30720
#define SMEM_TOTAL (STAGES * STG) // 184320

// ---------------------------------------------------------------------------
// Scratch (device globals: allocation-free kernel_launch)
// ---------------------------------------------------------------------------
__device__ __align__(256) __half g_A[(size_t)M_TOTAL * K_IN];   // fp16 activations
__device__ __align__(256) __half g_W[(size_t)N_OUT * K_IN];     // fp16 weights (exact)
__device__ float g_sumx[M_TOTAL];                                // per-row sum of fp16(x)

// ---------------------------------------------------------------------------
// PTX helpers (sm_80 baseline features only — compute_103 safe)
// ---------------------------------------------------------------------------
__device__ __forceinline__ uint32_t smem_u32(const void* p) {
    uint32_t a;
    asm("{ .reg .u64 t; cvta.to.shared.u64 t, %1; cvt.u32.u64 %0, t; }" : "=r"(a) : "l"(p));
    return a;
}
__device__ __forceinline__ void cp_async16(uint32_t dst, const void* src) {
    asm volatile("cp.async.cg.shared.global [%0], [%1], 16;" :: "r"(dst), "l"(src));
}
#define CP_COMMIT() asm volatile("cp.async.commit_group;")
#define CP_WAIT1()  asm volatile("cp.async.wait_group 1;")

__device__ __forceinline__ void ldsm_x4(uint32_t (&r)[4], uint32_t addr) {
    asm volatile("ldmatrix.sync.aligned.m8n8.x4.shared.b16 {%0,%1,%2,%3}, [%4];"
                 : "=r"(r[0]), "=r"(r[1]), "=r"(r[2]), "=r"(r[3]) : "r"(addr));
}
__device__ __forceinline__ void mma16816(float (&d)[4], const uint32_t (&a)[4],
                                         uint32_t b0, uint32_t b1) {
    asm volatile(
        "mma.sync.aligned.m16n8k16.row.col.f32.f16.f16.f32 "
        "{%0,%1,%2,%3}, {%4,%5,%6,%7}, {%8,%9}, {%0,%1,%2,%3};"
        : "+f"(d[0]), "+f"(d[1]), "+f"(d[2]), "+f"(d[3])
        : "r"(a[0]), "r"(a[1]), "r"(a[2]), "r"(a[3]), "r"(b0), "r"(b1));
}

// ---------------------------------------------------------------------------
// Fused prep kernel (single launch so ncu -s 5 lands on k_gemm)
// ---------------------------------------------------------------------------
__global__ void __launch_bounds__(256) k_prep(const float* __restrict__ in,
                                              const int* __restrict__ q) {
    int b = blockIdx.x;
    int t = threadIdx.x;
    if (b < M_TOTAL) {
        const float4* src = reinterpret_cast<const float4*>(in + (size_t)b * K_IN);
        uint2* dst = reinterpret_cast<uint2*>(g_A + (size_t)b * K_IN);
        float s = 0.f;
#pragma unroll
        for (int i = 0; i < 4; i++) {
            int e = i * 256 + t;
            float4 v = src[e];
            __half2 h0 = __floats2half2_rn(v.x, v.y);
            __half2 h1 = __floats2half2_rn(v.z, v.w);
            s += __low2float(h0) + __high2float(h0) + __low2float(h1) + __high2float(h1);
            uint2 p;
            p.x = *reinterpret_cast<uint32_t*>(&h0);
            p.y = *reinterpret_cast<uint32_t*>(&h1);
            dst[e] = p;
        }
#pragma unroll
        for (int off = 16; off; off >>= 1) s += __shfl_xor_sync(0xFFFFFFFFu, s, off);
        __shared__ float ws[8];
        if ((t & 31) == 0) ws[t >> 5] = s;
        __syncthreads();
        if (t == 0) {
            float tot = 0.f;
#pragma unroll
            for (int i = 0; i < 8; i++) tot += ws[i];
            g_sumx[b] = tot;
        }
    } else {
        int row = b - M_TOTAL;
        const int4* src = reinterpret_cast<const int4*>(q + (size_t)row * K_IN);
        uint2* dst = reinterpret_cast<uint2*>(g_W + (size_t)row * K_IN);
#pragma unroll
        for (int i = 0; i < 4; i++) {
            int e = i * 256 + t;
            int4 v = src[e];
            __half2 h0 = __floats2half2_rn((float)v.x, (float)v.y);
            __half2 h1 = __floats2half2_rn((float)v.z, (float)v.w);
            uint2 p;
            p.x = *reinterpret_cast<uint32_t*>(&h0);
            p.y = *reinterpret_cast<uint32_t*>(&h1);
            dst[e] = p;
        }
    }
}

// ---------------------------------------------------------------------------
// GEMM
// ---------------------------------------------------------------------------
__device__ __forceinline__ void load_stage(uint32_t s_base, const __half* Ag,
                                           const __half* Wg, int kt, int t) {
    uint32_t sA = s_base, sB = s_base + A_STG;
    int c = t & 3;            // 16B chunk within 64B row
    int r = t >> 2;           // 0..63
    const __half* asrc = Ag + (size_t)r * K_IN + kt * BK + c * 8;
    uint32_t adst = sA + r * LDS_B + c * 16;
    cp_async16(adst, asrc);
    cp_async16(adst + 64 * LDS_B, asrc + (size_t)64 * K_IN);
    const __half* bsrc = Wg + (size_t)r * K_IN + kt * BK + c * 8;
    uint32_t bdst = sB + r * LDS_B + c * 16;
#pragma unroll
    for (int i = 0; i < 4; i++)
        cp_async16(bdst + i * 64 * LDS_B, bsrc + (size_t)i * 64 * K_IN);
}

__global__ void __launch_bounds__(256, 1) k_gemm(
    const __half* __restrict__ pA, const __half* __restrict__ pW,
    float* __restrict__ out,
    const float* __restrict__ w_scale, const int* __restrict__ w_zp,
    const float* __restrict__ bias, const float* __restrict__ sumx)
{
    extern __shared__ char smem[];
    uint32_t sm0 = smem_u32(smem);
    int t = threadIdx.x;
    int wid = t >> 5;
    int l = t & 31;

    // grouped rasterization: 16 M-tiles per supercolumn (L2 reuse of W)
    int bid = blockIdx.x;
    const int group = GROUP_M * N_TILES;      // 688
    int g0 = bid / group;
    int rem = bid - g0 * group;
    int mtile = g0 * GROUP_M + (rem % GROUP_M);
    int ntile = rem / GROUP_M;

    int mbase = (wid & 1) * 64;               // 2 warps in M
    int nbase = (wid >> 1) * 64;              // 4 warps in N

    const __half* Ag = pA + (size_t)mtile * BM * K_IN;
    const __half* Wg = pW + (size_t)ntile * BN * K_IN;

    float acc[4][8][4];
#pragma unroll
    for (int a = 0; a < 4; a++)
#pragma unroll
        for (int b = 0; b < 8; b++)
#pragma unroll
            for (int c = 0; c < 4; c++) acc[a][b][c] = 0.f;

    // prologue: stages 0..3 as two commit groups {0,1} {2,3}
    load_stage(sm0 + 0 * STG, Ag, Wg, 0, t);
    load_stage(sm0 + 1 * STG, Ag, Wg, 1, t);
    CP_COMMIT();
    load_stage(sm0 + 2 * STG, Ag, Wg, 2, t);
    load_stage(sm0 + 3 * STG, Ag, Wg, 3, t);
    CP_COMMIT();

    // lane-invariant ldmatrix address pieces
    uint32_t a_lane_off = (uint32_t)((l & 15) + mbase) * LDS_B + ((l >> 4) << 4);
    uint32_t b_lane_off = (uint32_t)((l & 7) + ((l >> 4) << 3) + nbase) * LDS_B
                        + (((l >> 3) & 1) << 4);

    // window loop: one barrier per TWO k-iterations (warps skew within window)
    int buf = 0;                               // buffer index of stage w
    for (int w = 0; w < K_ITERS; w += 2) {
        CP_WAIT1();                            // stages {w, w+1} resident
        __syncthreads();                       // producers may now overwrite bufs read in w-2

        int buf1 = buf + 1; if (buf1 >= STAGES) buf1 -= STAGES;

        // ---- sub-iteration 0 (stage w) ----
        {
            uint32_t sA = sm0 + buf * STG;
            uint32_t sB = sA + A_STG;
            uint32_t af[2][4][4];
            uint32_t bf[2][4][4];
#pragma unroll
            for (int k16 = 0; k16 < 2; k16++) {
                uint32_t koff = (uint32_t)k16 * 32;
#pragma unroll
                for (int mi = 0; mi < 4; mi++)
                    ldsm_x4(af[k16][mi], sA + koff + a_lane_off + mi * 16 * LDS_B);
#pragma unroll
                for (int ni = 0; ni < 4; ni++)
                    ldsm_x4(bf[k16][ni], sB + koff + b_lane_off + ni * 16 * LDS_B);
            }

            // producer: stages w+4, w+5 into buffers freed at window w-2
            if (w + 4 < K_ITERS) {
                int nb0 = buf + 4; if (nb0 >= STAGES) nb0 -= STAGES;
                int nb1 = buf + 5; if (nb1 >= STAGES) nb1 -= STAGES;
                load_stage(sm0 + nb0 * STG, Ag, Wg, w + 4, t);
                load_stage(sm0 + nb1 * STG, Ag, Wg, w + 5, t);
            }
            CP_COMMIT();

#pragma unroll
            for (int k16 = 0; k16 < 2; k16++)
#pragma unroll
                for (int mi = 0; mi < 4; mi++)
#pragma unroll
                    for (int ni = 0; ni < 4; ni++) {
                        mma16816(acc[mi][2 * ni],     af[k16][mi], bf[k16][ni][0], bf[k16][ni][1]);
                        mma16816(acc[mi][2 * ni + 1], af[k16][mi], bf[k16][ni][2], bf[k16][ni][3]);
                    }
        }

        // ---- sub-iteration 1 (stage w+1) ----
        {
            uint32_t sA = sm0 + buf1 * STG;
            uint32_t sB = sA + A_STG;
            uint32_t af[2][4][4];
            uint32_t bf[2][4][4];
#pragma unroll
            for (int k16 = 0; k16 < 2; k16++) {
                uint32_t koff = (uint32_t)k16 * 32;
#pragma unroll
                for (int mi = 0; mi < 4; mi++)
                    ldsm_x4(af[k16][mi], sA + koff + a_lane_off + mi * 16 * LDS_B);
#pragma unroll
                for (int ni = 0; ni < 4; ni++)
                    ldsm_x4(bf[k16][ni], sB + koff + b_lane_off + ni * 16 * LDS_B);
            }
#pragma unroll
            for (int k16 = 0; k16 < 2; k16++)
#pragma unroll
                for (int mi = 0; mi < 4; mi++)
#pragma unroll
                    for (int ni = 0; ni < 4; ni++) {
                        mma16816(acc[mi][2 * ni],     af[k16][mi], bf[k16][ni][0], bf[k16][ni][1]);
                        mma16816(acc[mi][2 * ni + 1], af[k16][mi], bf[k16][ni][2], bf[k16][ni][3]);
                    }
        }

        buf += 2; if (buf >= STAGES) buf -= STAGES;
    }

    // ------------------ epilogue ------------------
    int g = l >> 2;
    int t2 = (l & 3) << 1;

    float scx[8][2], zpx[8][2], bix[8][2];
#pragma unroll
    for (int nj = 0; nj < 8; nj++) {
        int n = ntile * BN + nbase + nj * 8 + t2;
        float2 sc = *reinterpret_cast<const float2*>(w_scale + n);
        int2   zp = *reinterpret_cast<const int2*>(w_zp + n);
        float2 bb = *reinterpret_cast<const float2*>(bias + n);
        scx[nj][0] = sc.x; scx[nj][1] = sc.y;
        zpx[nj][0] = (float)zp.x; zpx[nj][1] = (float)zp.y;
        bix[nj][0] = bb.x; bix[nj][1] = bb.y;
    }

#pragma unroll
    for (int mi = 0; mi < 4; mi++) {
        int m0 = mtile * BM + mbase + mi * 16 + g;
        float sx0 = sumx[m0];
        float sx1 = sumx[m0 + 8];
        float* o0 = out + (size_t)m0 * N_OUT + ntile * BN + nbase + t2;
        float* o1 = o0 + (size_t)8 * N_OUT;
#pragma unroll
        for (int nj = 0; nj < 8; nj++) {
            float2 v0, v1;
            v0.x = (acc[mi][nj][0] - zpx[nj][0] * sx0) * scx[nj][0] + bix[nj][0];
            v0.y = (acc[mi][nj][1] - zpx[nj][1] * sx0) * scx[nj][1] + bix[nj][1];
            v1.x = (acc[mi][nj][2] - zpx[nj][0] * sx1) * scx[nj][0] + bix[nj][0];
            v1.y = (acc[mi][nj][3] - zpx[nj][1] * sx1) * scx[nj][1] + bix[nj][1];
            *reinterpret_cast<float2*>(o0 + nj * 8) = v0;
            *reinterpret_cast<float2*>(o1 + nj * 8) = v1;
        }
    }
}

// ---------------------------------------------------------------------------
// Host
// ---------------------------------------------------------------------------
extern "C" void kernel_launch(void* const* d_in, const int* in_sizes, int n_in,
                              void* d_out, int out_size) {
    const float* input   = (const float*)d_in[0];
    const int*   qweight = (const int*)d_in[1];
    const float* w_scale = (const float*)d_in[2];
    const int*   w_zp    = (const int*)d_in[3];
    const float* bias    = (const float*)d_in[4];
    float*       out     = (float*)d_out;

    void *pA = nullptr, *pW = nullptr, *pS = nullptr;
    cudaGetSymbolAddress(&pA, g_A);
    cudaGetSymbolAddress(&pW, g_W);
    cudaGetSymbolAddress(&pS, g_sumx);

    k_prep<<<M_TOTAL + N_OUT, 256>>>(input, qweight);

    cudaFuncSetAttribute(k_gemm, cudaFuncAttributeMaxDynamicSharedMemorySize, SMEM_TOTAL);
    k_gemm<<<M_TILES * N_TILES, 256, SMEM_TOTAL>>>(
        (const __half*)pA, (const __half*)pW, out, w_scale, w_zp, bias, (const float*)pS);
}

// round 8
// speedup vs baseline: 6.0228x; 1.3707x over previous
#include <cuda_runtime.h>
#include <cuda_fp16.h>
#include <cstdint>

// ---------------------------------------------------------------------------
// Problem dims
// ---------------------------------------------------------------------------
#define M_TOTAL 8192
#define K_IN    4096
#define N_OUT   11008

// GEMM tiling: 128x256x32 CTA, 8 warps @ 64x64 warp tiles, 1 CTA/SM
#define BM 128
#define BN 256
#define BK 32                    // halfs per k-stage
#define STAGES 5
#define K_ITERS (K_IN / BK)      // 128
#define M_TILES (M_TOTAL / BM)   // 64
#define N_TILES (N_OUT / BN)     // 43
#define GROUP_M 16

#define LDS_B 80                 // smem bytes per 32-half row (64B + 16B pad)
#define A_STG (BM * LDS_B)       // 10240
#define B_STG (BN * LDS_B)       // 20480
#define STG   (A_STG + B_STG)    // 30720
#define SMEM_TOTAL (STAGES * STG) // 153600

// ---------------------------------------------------------------------------
// Scratch (device globals: allocation-free kernel_launch)
// ---------------------------------------------------------------------------
__device__ __align__(256) __half g_A[(size_t)M_TOTAL * K_IN];   // fp16 activations
__device__ __align__(256) __half g_W[(size_t)N_OUT * K_IN];     // fp16 weights (exact)
__device__ float g_sumx[M_TOTAL];                                // per-row sum of fp16(x)

// ---------------------------------------------------------------------------
// PTX helpers (sm_80 baseline features only — compute_103 safe)
// ---------------------------------------------------------------------------
__device__ __forceinline__ uint32_t smem_u32(const void* p) {
    uint32_t a;
    asm("{ .reg .u64 t; cvta.to.shared.u64 t, %1; cvt.u32.u64 %0, t; }" : "=r"(a) : "l"(p));
    return a;
}
__device__ __forceinline__ void cp_async16(uint32_t dst, const void* src) {
    asm volatile("cp.async.cg.shared.global [%0], [%1], 16;" :: "r"(dst), "l"(src));
}
#define CP_COMMIT() asm volatile("cp.async.commit_group;")
#define CP_WAIT2()  asm volatile("cp.async.wait_group 2;")

__device__ __forceinline__ void ldsm_x4(uint32_t (&r)[4], uint32_t addr) {
    asm volatile("ldmatrix.sync.aligned.m8n8.x4.shared.b16 {%0,%1,%2,%3}, [%4];"
                 : "=r"(r[0]), "=r"(r[1]), "=r"(r[2]), "=r"(r[3]) : "r"(addr));
}
__device__ __forceinline__ void mma16816(float (&d)[4], const uint32_t (&a)[4],
                                         uint32_t b0, uint32_t b1) {
    asm volatile(
        "mma.sync.aligned.m16n8k16.row.col.f32.f16.f16.f32 "
        "{%0,%1,%2,%3}, {%4,%5,%6,%7}, {%8,%9}, {%0,%1,%2,%3};"
        : "+f"(d[0]), "+f"(d[1]), "+f"(d[2]), "+f"(d[3])
        : "r"(a[0]), "r"(a[1]), "r"(a[2]), "r"(a[3]), "r"(b0), "r"(b1));
}

// ---------------------------------------------------------------------------
// Fused prep kernel (single launch so ncu -s 5 lands on k_gemm)
// ---------------------------------------------------------------------------
__global__ void __launch_bounds__(256) k_prep(const float* __restrict__ in,
                                              const int* __restrict__ q) {
    int b = blockIdx.x;
    int t = threadIdx.x;
    if (b < M_TOTAL) {
        const float4* src = reinterpret_cast<const float4*>(in + (size_t)b * K_IN);
        uint2* dst = reinterpret_cast<uint2*>(g_A + (size_t)b * K_IN);
        float s = 0.f;
#pragma unroll
        for (int i = 0; i < 4; i++) {
            int e = i * 256 + t;
            float4 v = src[e];
            __half2 h0 = __floats2half2_rn(v.x, v.y);
            __half2 h1 = __floats2half2_rn(v.z, v.w);
            s += __low2float(h0) + __high2float(h0) + __low2float(h1) + __high2float(h1);
            uint2 p;
            p.x = *reinterpret_cast<uint32_t*>(&h0);
            p.y = *reinterpret_cast<uint32_t*>(&h1);
            dst[e] = p;
        }
#pragma unroll
        for (int off = 16; off; off >>= 1) s += __shfl_xor_sync(0xFFFFFFFFu, s, off);
        __shared__ float ws[8];
        if ((t & 31) == 0) ws[t >> 5] = s;
        __syncthreads();
        if (t == 0) {
            float tot = 0.f;
#pragma unroll
            for (int i = 0; i < 8; i++) tot += ws[i];
            g_sumx[b] = tot;
        }
    } else {
        int row = b - M_TOTAL;
        const int4* src = reinterpret_cast<const int4*>(q + (size_t)row * K_IN);
        uint2* dst = reinterpret_cast<uint2*>(g_W + (size_t)row * K_IN);
#pragma unroll
        for (int i = 0; i < 4; i++) {
            int e = i * 256 + t;
            int4 v = src[e];
            __half2 h0 = __floats2half2_rn((float)v.x, (float)v.y);
            __half2 h1 = __floats2half2_rn((float)v.z, (float)v.w);
            uint2 p;
            p.x = *reinterpret_cast<uint32_t*>(&h0);
            p.y = *reinterpret_cast<uint32_t*>(&h1);
            dst[e] = p;
        }
    }
}

// ---------------------------------------------------------------------------
// GEMM
// ---------------------------------------------------------------------------
__device__ __forceinline__ void load_stage(uint32_t s_base, const __half* Ag,
                                           const __half* Wg, int kt, int t) {
    uint32_t sA = s_base, sB = s_base + A_STG;
    int c = t & 3;            // 16B chunk within 64B row
    int r = t >> 2;           // 0..63
    const __half* asrc = Ag + (size_t)r * K_IN + kt * BK + c * 8;
    uint32_t adst = sA + r * LDS_B + c * 16;
    cp_async16(adst, asrc);
    cp_async16(adst + 64 * LDS_B, asrc + (size_t)64 * K_IN);
    const __half* bsrc = Wg + (size_t)r * K_IN + kt * BK + c * 8;
    uint32_t bdst = sB + r * LDS_B + c * 16;
#pragma unroll
    for (int i = 0; i < 4; i++)
        cp_async16(bdst + i * 64 * LDS_B, bsrc + (size_t)i * 64 * K_IN);
}

__global__ void __launch_bounds__(256, 1) k_gemm(
    const __half* __restrict__ pA, const __half* __restrict__ pW,
    float* __restrict__ out,
    const float* __restrict__ w_scale, const int* __restrict__ w_zp,
    const float* __restrict__ bias, const float* __restrict__ sumx)
{
    extern __shared__ char smem[];
    uint32_t sm0 = smem_u32(smem);
    int t = threadIdx.x;
    int wid = t >> 5;
    int l = t & 31;

    // grouped rasterization: 16 M-tiles per supercolumn (L2 reuse of W)
    int bid = blockIdx.x;
    const int group = GROUP_M * N_TILES;      // 688
    int g0 = bid / group;
    int rem = bid - g0 * group;
    int mtile = g0 * GROUP_M + (rem % GROUP_M);
    int ntile = rem / GROUP_M;

    int mbase = (wid & 1) * 64;               // 2 warps in M
    int nbase = (wid >> 1) * 64;              // 4 warps in N

    const __half* Ag = pA + (size_t)mtile * BM * K_IN;
    const __half* Wg = pW + (size_t)ntile * BN * K_IN;

    float acc[4][8][4];
#pragma unroll
    for (int a = 0; a < 4; a++)
#pragma unroll
        for (int b = 0; b < 8; b++)
#pragma unroll
            for (int c = 0; c < 4; c++) acc[a][b][c] = 0.f;

    // prologue: fill 4 stages, one commit group each
#pragma unroll
    for (int s = 0; s < STAGES - 1; s++) {
        load_stage(sm0 + s * STG, Ag, Wg, s, t);
        CP_COMMIT();
    }

    // lane-invariant ldmatrix address pieces
    uint32_t a_lane_off = (uint32_t)((l & 15) + mbase) * LDS_B + ((l >> 4) << 4);
    uint32_t b_lane_off = (uint32_t)((l & 7) + ((l >> 4) << 3) + nbase) * LDS_B
                        + (((l >> 3) & 1) << 4);

    // wait for stages 0,1 and prefetch k16=0 fragments of stage 0
    CP_WAIT2();
    __syncthreads();

    uint32_t aCur[4][4], bCur[4][4];   // fragments for current k16
    uint32_t aNxt[4][4], bNxt[4][4];   // fragments for the other k16
    {
        uint32_t sA = sm0, sB = sm0 + A_STG;
#pragma unroll
        for (int mi = 0; mi < 4; mi++)
            ldsm_x4(aCur[mi], sA + a_lane_off + mi * 16 * LDS_B);
#pragma unroll
        for (int ni = 0; ni < 4; ni++)
            ldsm_x4(bCur[ni], sB + b_lane_off + ni * 16 * LDS_B);
    }

    int buf = 0;
    for (int kt = 0; kt < K_ITERS; kt++) {
        uint32_t sA = sm0 + buf * STG;
        uint32_t sB = sA + A_STG;

        // (1) LDSM k16=1 fragments -> nxt (no consumer until step 6)
#pragma unroll
        for (int mi = 0; mi < 4; mi++)
            ldsm_x4(aNxt[mi], sA + 32 + a_lane_off + mi * 16 * LDS_B);
#pragma unroll
        for (int ni = 0; ni < 4; ni++)
            ldsm_x4(bNxt[ni], sB + 32 + b_lane_off + ni * 16 * LDS_B);

        // (2) producer: stage kt+4 into buffer freed after last window
        if (kt + STAGES - 1 < K_ITERS) {
            int nb = buf + (STAGES - 1); if (nb >= STAGES) nb -= STAGES;
            load_stage(sm0 + nb * STG, Ag, Wg, kt + STAGES - 1, t);
        }
        CP_COMMIT();

        // (3) 32 HMMAs on cur (k16=0) — operands ready, overlap LDSM/cp.async
#pragma unroll
        for (int mi = 0; mi < 4; mi++)
#pragma unroll
            for (int ni = 0; ni < 4; ni++) {
                mma16816(acc[mi][2 * ni],     aCur[mi], bCur[ni][0], bCur[ni][1]);
                mma16816(acc[mi][2 * ni + 1], aCur[mi], bCur[ni][2], bCur[ni][3]);
            }

        // (4) stage kt+1 (and kt+2) resident; free buffer (kt)%STAGES for overwrite
        CP_WAIT2();
        __syncthreads();

        // (5) prefetch kt+1's k16=0 fragments -> cur (safe: stage kt+1 visible,
        //     its buffer not written until window kt+1's producer at earliest)
        int nbuf = buf + 1; if (nbuf == STAGES) nbuf = 0;
        if (kt + 1 < K_ITERS) {
            uint32_t sA2 = sm0 + nbuf * STG;
            uint32_t sB2 = sA2 + A_STG;
#pragma unroll
            for (int mi = 0; mi < 4; mi++)
                ldsm_x4(aCur[mi], sA2 + a_lane_off + mi * 16 * LDS_B);
#pragma unroll
            for (int ni = 0; ni < 4; ni++)
                ldsm_x4(bCur[ni], sB2 + b_lane_off + ni * 16 * LDS_B);
        }

        // (6) 32 HMMAs on nxt (k16=1) — loaded in (1), independent of (5)
#pragma unroll
        for (int mi = 0; mi < 4; mi++)
#pragma unroll
            for (int ni = 0; ni < 4; ni++) {
                mma16816(acc[mi][2 * ni],     aNxt[mi], bNxt[ni][0], bNxt[ni][1]);
                mma16816(acc[mi][2 * ni + 1], aNxt[mi], bNxt[ni][2], bNxt[ni][3]);
            }

        buf = nbuf;
    }

    // ------------------ epilogue ------------------
    int g = l >> 2;
    int t2 = (l & 3) << 1;

    float scx[8][2], zpx[8][2], bix[8][2];
#pragma unroll
    for (int nj = 0; nj < 8; nj++) {
        int n = ntile * BN + nbase + nj * 8 + t2;
        float2 sc = *reinterpret_cast<const float2*>(w_scale + n);
        int2   zp = *reinterpret_cast<const int2*>(w_zp + n);
        float2 bb = *reinterpret_cast<const float2*>(bias + n);
        scx[nj][0] = sc.x; scx[nj][1] = sc.y;
        zpx[nj][0] = (float)zp.x; zpx[nj][1] = (float)zp.y;
        bix[nj][0] = bb.x; bix[nj][1] = bb.y;
    }

#pragma unroll
    for (int mi = 0; mi < 4; mi++) {
        int m0 = mtile * BM + mbase + mi * 16 + g;
        float sx0 = sumx[m0];
        float sx1 = sumx[m0 + 8];
        float* o0 = out + (size_t)m0 * N_OUT + ntile * BN + nbase + t2;
        float* o1 = o0 + (size_t)8 * N_OUT;
#pragma unroll
        for (int nj = 0; nj < 8; nj++) {
            float2 v0, v1;
            v0.x = (acc[mi][nj][0] - zpx[nj][0] * sx0) * scx[nj][0] + bix[nj][0];
            v0.y = (acc[mi][nj][1] - zpx[nj][1] * sx0) * scx[nj][1] + bix[nj][1];
            v1.x = (acc[mi][nj][2] - zpx[nj][0] * sx1) * scx[nj][0] + bix[nj][0];
            v1.y = (acc[mi][nj][3] - zpx[nj][1] * sx1) * scx[nj][1] + bix[nj][1];
            *reinterpret_cast<float2*>(o0 + nj * 8) = v0;
            *reinterpret_cast<float2*>(o1 + nj * 8) = v1;
        }
    }
}

// ---------------------------------------------------------------------------
// Host
// ---------------------------------------------------------------------------
extern "C" void kernel_launch(void* const* d_in, const int* in_sizes, int n_in,
                              void* d_out, int out_size) {
    const float* input   = (const float*)d_in[0];
    const int*   qweight = (const int*)d_in[1];
    const float* w_scale = (const float*)d_in[2];
    const int*   w_zp    = (const int*)d_in[3];
    const float* bias    = (const float*)d_in[4];
    float*       out     = (float*)d_out;

    void *pA = nullptr, *pW = nullptr, *pS = nullptr;
    cudaGetSymbolAddress(&pA, g_A);
    cudaGetSymbolAddress(&pW, g_W);
    cudaGetSymbolAddress(&pS, g_sumx);

    k_prep<<<M_TOTAL + N_OUT, 256>>>(input, qweight);

    cudaFuncSetAttribute(k_gemm, cudaFuncAttributeMaxDynamicSharedMemorySize, SMEM_TOTAL);
    k_gemm<<<M_TILES * N_TILES, 256, SMEM_TOTAL>>>(
        (const __half*)pA, (const __half*)pW, out, w_scale, w_zp, bias, (const float*)pS);
}